// round 1
// baseline (speedup 1.0000x reference)
#include <cuda_runtime.h>
#include <cstdint>

#define NRMAX   512
#define CHUNK   64
#define TPB     512
#define HD      128
#define RD      64
#define EMB_STRIDE 130          // float2 stride (padded to dodge bank conflicts)
#define MAXCHUNKS 2048
#define BMAX    65536

// persistent device scratch (no allocations allowed)
__device__ int g_count[NRMAX];
__device__ int g_cursor[NRMAX];
__device__ int g_chunk_rel[MAXCHUNKS];
__device__ int g_chunk_start[MAXCHUNKS];
__device__ int g_chunk_cnt[MAXCHUNKS];
__device__ int g_num_chunks;
__device__ int g_perm[BMAX];

// ---------- packed f32x2 helpers (FFMA2 via PTX; ptxas won't auto-fuse) ----------
__device__ __forceinline__ unsigned long long pack2(float x, float y) {
    unsigned long long r;
    asm("mov.b64 %0, {%1, %2};" : "=l"(r) : "f"(x), "f"(y));
    return r;
}
__device__ __forceinline__ void ffma2(unsigned long long& d,
                                      unsigned long long a, unsigned long long b) {
    asm("fma.rn.f32x2 %0, %1, %2, %0;" : "+l"(d) : "l"(a), "l"(b));
}
__device__ __forceinline__ float2 unpack2(unsigned long long v) {
    float x, y;
    asm("mov.b64 {%0, %1}, %2;" : "=f"(x), "=f"(y) : "l"(v));
    return make_float2(x, y);
}

// ---------- pass 1: zero histogram ----------
__global__ void k_zero() {
    if (threadIdx.x < NRMAX) g_count[threadIdx.x] = 0;
}

// ---------- pass 2: histogram over relations ----------
__global__ void k_hist(const int* __restrict__ rel, int n) {
    int i = blockIdx.x * blockDim.x + threadIdx.x;
    if (i < n) atomicAdd(&g_count[rel[i]], 1);
}

// ---------- pass 3: exclusive scan + chunk plan (single block) ----------
__global__ void k_plan(int nr) {
    __shared__ int sc[NRMAX];
    int t = threadIdx.x;
    int c = (t < nr) ? g_count[t] : 0;

    // inclusive scan of counts
    sc[t] = c; __syncthreads();
    for (int off = 1; off < NRMAX; off <<= 1) {
        int v = (t >= off) ? sc[t - off] : 0;
        __syncthreads();
        sc[t] += v;
        __syncthreads();
    }
    int excl = sc[t] - c;
    if (t < nr) g_cursor[t] = excl;

    // scan of per-relation chunk counts
    int nch = (c + CHUNK - 1) / CHUNK;
    __syncthreads();
    sc[t] = nch; __syncthreads();
    for (int off = 1; off < NRMAX; off <<= 1) {
        int v = (t >= off) ? sc[t - off] : 0;
        __syncthreads();
        sc[t] += v;
        __syncthreads();
    }
    int cbase = sc[t] - nch;
    for (int k = 0; k < nch; k++) {
        int id = cbase + k;
        g_chunk_rel[id]   = t;
        g_chunk_start[id] = excl + k * CHUNK;
        int rem = c - k * CHUNK;
        g_chunk_cnt[id]   = (rem < CHUNK) ? rem : CHUNK;
    }
    if (t == NRMAX - 1) g_num_chunks = sc[t];
}

// ---------- pass 4: scatter batch indices into relation buckets ----------
__global__ void k_scatter(const int* __restrict__ rel, int n) {
    int i = blockIdx.x * blockDim.x + threadIdx.x;
    if (i < n) {
        int p = atomicAdd(&g_cursor[rel[i]], 1);
        g_perm[p] = i;
    }
}

// ---------- pass 5: compute ----------
// block = one chunk (<=64 elements, one relation). 16 warps.
// warp handles 4 elements; lane: e_sub = lane>>3, rq = lane&7 (owns r = rq*8..rq*8+7).
__global__ __launch_bounds__(TPB, 2) void k_compute(
    const int*   __restrict__ src,
    const int*   __restrict__ dst,
    const float* __restrict__ ent,
    const float* __restrict__ relemb,
    const float* __restrict__ proj,
    float*       __restrict__ out)
{
    extern __shared__ float smem[];
    float*  s_proj = smem;                               // HD*RD floats (32 KB)
    float2* s_emb  = (float2*)(smem + HD * RD);          // CHUNK * EMB_STRIDE float2
    __shared__ int s_idx[CHUNK];

    int cid = blockIdx.x;
    if (cid >= g_num_chunks) return;
    int r_id  = g_chunk_rel[cid];
    int start = g_chunk_start[cid];
    int cnt   = g_chunk_cnt[cid];

    // stage proj tile [h][r] (row-major, matches global layout)
    {
        const float4* p4  = (const float4*)(proj + (size_t)r_id * (HD * RD));
        float4*       sp4 = (float4*)s_proj;
        #pragma unroll
        for (int i = threadIdx.x; i < HD * RD / 4; i += TPB) sp4[i] = p4[i];
    }
    if (threadIdx.x < CHUNK) {
        int e = threadIdx.x;
        s_idx[e] = (e < cnt) ? g_perm[start + e] : -1;
    }
    __syncthreads();

    // stage interleaved {src,dst} embeddings: 8 threads per element
    {
        int e   = threadIdx.x >> 3;
        int sub = threadIdx.x & 7;
        if (e < cnt) {
            int idx = s_idx[e];
            const float4* sr = (const float4*)(ent + (size_t)src[idx] * HD);
            const float4* dr = (const float4*)(ent + (size_t)dst[idx] * HD);
            float2* er = s_emb + e * EMB_STRIDE;
            #pragma unroll
            for (int j = 0; j < 4; j++) {
                int q = sub * 4 + j;
                float4 sv = sr[q];
                float4 dv = dr[q];
                er[q * 4 + 0] = make_float2(sv.x, dv.x);
                er[q * 4 + 1] = make_float2(sv.y, dv.y);
                er[q * 4 + 2] = make_float2(sv.z, dv.z);
                er[q * 4 + 3] = make_float2(sv.w, dv.w);
            }
        }
    }
    __syncthreads();

    int warp  = threadIdx.x >> 5;
    int lane  = threadIdx.x & 31;
    int rq    = lane & 7;
    int e     = warp * 4 + (lane >> 3);
    if (e >= cnt) return;
    unsigned gmask = 0xFFu << (lane & 24);   // the 8-lane group of this element

    unsigned long long as[4] = {0,0,0,0};
    unsigned long long ad[4] = {0,0,0,0};
    const float4* pr = (const float4*)s_proj + rq * 2;   // row stride = 16 float4
    const float2* er = s_emb + e * EMB_STRIDE;

    #pragma unroll 4
    for (int h = 0; h < HD; h++) {
        float2 ed = er[h];                    // {src[h], dst[h]} broadcast in group
        float4 p0 = pr[h * 16];
        float4 p1 = pr[h * 16 + 1];
        unsigned long long se2 = pack2(ed.x, ed.x);
        unsigned long long de2 = pack2(ed.y, ed.y);
        unsigned long long b0 = pack2(p0.x, p0.y);
        unsigned long long b1 = pack2(p0.z, p0.w);
        unsigned long long b2 = pack2(p1.x, p1.y);
        unsigned long long b3 = pack2(p1.z, p1.w);
        ffma2(as[0], se2, b0); ffma2(as[1], se2, b1);
        ffma2(as[2], se2, b2); ffma2(as[3], se2, b3);
        ffma2(ad[0], de2, b0); ffma2(ad[1], de2, b1);
        ffma2(ad[2], de2, b2); ffma2(ad[3], de2, b3);
    }

    // unpack 8 r-values each
    float s[8], d[8];
    #pragma unroll
    for (int k = 0; k < 4; k++) {
        float2 v = unpack2(as[k]); s[2*k] = v.x; s[2*k+1] = v.y;
        float2 w = unpack2(ad[k]); d[2*k] = w.x; d[2*k+1] = w.y;
    }
    float ss = 0.f, dd = 0.f;
    #pragma unroll
    for (int k = 0; k < 8; k++) { ss += s[k]*s[k]; dd += d[k]*d[k]; }
    #pragma unroll
    for (int o = 4; o > 0; o >>= 1) {
        ss += __shfl_xor_sync(gmask, ss, o);
        dd += __shfl_xor_sync(gmask, dd, o);
    }
    float inv_s = 1.f / fmaxf(sqrtf(ss), 1e-12f);
    float inv_d = 1.f / fmaxf(sqrtf(dd), 1e-12f);

    const float4* rr = (const float4*)(relemb + (size_t)r_id * RD) + rq * 2;
    float4 r0 = rr[0], r1 = rr[1];
    float rv[8] = {r0.x, r0.y, r0.z, r0.w, r1.x, r1.y, r1.z, r1.w};

    float sc = 0.f;
    #pragma unroll
    for (int k = 0; k < 8; k++) {
        float df = s[k] * inv_s + rv[k] - d[k] * inv_d;
        sc += df * df;
    }
    #pragma unroll
    for (int o = 4; o > 0; o >>= 1) sc += __shfl_xor_sync(gmask, sc, o);

    if (rq == 0) out[s_idx[e]] = sqrtf(sc);
}

// ---------- launch ----------
extern "C" void kernel_launch(void* const* d_in, const int* in_sizes, int n_in,
                              void* d_out, int out_size) {
    const int*   src = (const int*)d_in[0];
    const int*   rel = (const int*)d_in[1];
    const int*   dst = (const int*)d_in[2];
    const float* ent = (const float*)d_in[3];
    const float* rle = (const float*)d_in[4];
    const float* prj = (const float*)d_in[5];
    float*       out = (float*)d_out;

    int B  = in_sizes[0];
    int NR = in_sizes[4] / RD;

    const int SMEM_BYTES = HD * RD * 4 + CHUNK * EMB_STRIDE * 8;  // 99328
    cudaFuncSetAttribute(k_compute, cudaFuncAttributeMaxDynamicSharedMemorySize,
                         SMEM_BYTES);

    int gB = (B + 255) / 256;
    int max_chunks = NR + (B + CHUNK - 1) / CHUNK;
    if (max_chunks > MAXCHUNKS) max_chunks = MAXCHUNKS;

    k_zero<<<1, NRMAX>>>();
    k_hist<<<gB, 256>>>(rel, B);
    k_plan<<<1, NRMAX>>>(NR);
    k_scatter<<<gB, 256>>>(rel, B);
    k_compute<<<max_chunks, TPB, SMEM_BYTES>>>(src, dst, ent, rle, prj, out);
}